// round 7
// baseline (speedup 1.0000x reference)
#include <cuda_runtime.h>
#include <math.h>
#include <stdint.h>

#define E_    32
#define TOPK  6
#define H_    2048
#define I_    1024
#define T_    2048
#define CAP_  768
#define SCALE_ 1.5f

// ---------------- scratch (device globals; no allocation allowed) ----------------
__device__ int   d_cnt[E_];
__device__ int   d_src[E_ * CAP_];        // slot -> token
__device__ int   d_slot[T_ * TOPK];       // e*CAP_+pos, or -1 if dropped
__device__ float d_wt[T_ * TOPK];         // normalized * SCALE_
__device__ float d_inter[(size_t)E_ * CAP_ * I_];   // silu(g)*u per expert
__device__ float d_sinter[(size_t)T_ * I_];         // shared-expert intermediate
__device__ float d_yb[(size_t)E_ * CAP_ * H_];      // expert outputs

// =================== portable PTX helpers (compute_103-safe, sm_80+) ===================
__device__ __forceinline__ uint32_t tf32r(float f) {
    uint32_t r; asm("cvt.rna.tf32.f32 %0, %1;" : "=r"(r) : "f"(f)); return r;
}
__device__ __forceinline__ float tf32f(float f) {
    return __uint_as_float(tf32r(f));
}
__device__ __forceinline__ void mma_tf32(float* c, const uint32_t* a, const uint32_t* b) {
    asm volatile(
        "mma.sync.aligned.m16n8k8.row.col.f32.tf32.tf32.f32 "
        "{%0,%1,%2,%3}, {%4,%5,%6,%7}, {%8,%9}, {%0,%1,%2,%3};"
        : "+f"(c[0]), "+f"(c[1]), "+f"(c[2]), "+f"(c[3])
        : "r"(a[0]), "r"(a[1]), "r"(a[2]), "r"(a[3]), "r"(b[0]), "r"(b[1]));
}

// ---------------- init ----------------
__global__ void init_kernel() {
    if (threadIdx.x < E_) d_cnt[threadIdx.x] = 0;
}

// ---------------- router ----------------
__global__ void router_kernel(const float* __restrict__ x,
                              const float* __restrict__ gw,
                              const float* __restrict__ bias) {
    int t = blockIdx.x;
    const float4* h4 = (const float4*)(x + (size_t)t * H_);
    __shared__ float sc[E_];
    __shared__ float sb[E_];
    int warp = threadIdx.x >> 5, lane = threadIdx.x & 31;

    for (int e = warp; e < E_; e += 4) {
        const float4* w4 = (const float4*)(gw + (size_t)e * H_);
        float s = 0.f;
        for (int i = lane; i < H_ / 4; i += 32) {
            float4 a = h4[i], b = w4[i];
            s += a.x * b.x + a.y * b.y + a.z * b.z + a.w * b.w;
        }
        #pragma unroll
        for (int o = 16; o > 0; o >>= 1) s += __shfl_xor_sync(0xffffffffu, s, o);
        if (lane == 0) {
            float sp = (s > 15.f) ? s : log1pf(expf(s));
            sc[e] = sqrtf(sp);
        }
    }
    __syncthreads();
    if (threadIdx.x < E_) sb[threadIdx.x] = sc[threadIdx.x] + bias[threadIdx.x];
    __syncthreads();

    if (threadIdx.x == 0) {
        int   idx[TOPK];
        float wsum = 0.f;
        for (int k = 0; k < TOPK; k++) {
            int best = 0; float bv = -1e30f;
            for (int e = 0; e < E_; e++)
                if (sb[e] > bv) { bv = sb[e]; best = e; }
            idx[k] = best;
            sb[best] = -1e30f;
            wsum += sc[best];
        }
        float inv = SCALE_ / wsum;
        for (int k = 0; k < TOPK; k++) {
            int e = idx[k];
            int pos = atomicAdd(&d_cnt[e], 1);
            if (pos < CAP_) {
                d_slot[t * TOPK + k] = e * CAP_ + pos;
                d_src[e * CAP_ + pos] = t;
            } else {
                d_slot[t * TOPK + k] = -1;
            }
            d_wt[t * TOPK + k] = sc[e] * inv;
        }
    }
}

// =================== tf32 mma.sync GEMM, fragment-layout smem ===================
// FUSED=1: C_g, C_u [128 x 64] = A[128,K=2048] @ {Bg,Bu}^T; SwiGLU fused -> d_inter/d_sinter
// FUSED=0: C [128 x 128] = A[128,K=1024] @ B^T (down proj) -> d_yb / out
//
// smem per stage: A: 32 blocks (8 mb x 4 ks) of 128 floats, stride 132 (pad 4)
//                 B: 64 blocks (16 cb x 4 ks) of 64 floats, stride 66 (pad 2)
// Fragment blocks hold data pre-converted to tf32 in EXACTLY mma fragment order:
//   A block (mb,ks): addr = lane*4 + reg, reg = hi + 2*half
//   B block (cb,ks): addr = lane*2 + half
// Inner loop: ld.shared.v4 (A) / v2 (B), zero cvt, conflict-free.

#define A_FLOATS 4224               // 32 * 132
#define B_FLOATS 4224               // 64 * 66
#define STG_FLOATS (A_FLOATS + B_FLOATS)
#define STG_BYTES (STG_FLOATS * 4)  // 33792
#define SMEM_G2   (2 * STG_BYTES)   // 67584

template<bool FUSED>
__global__ __launch_bounds__(256, 1)
void gemm2(const float* __restrict__ x,
           const float* __restrict__ wR1, const float* __restrict__ wR2,
           const float* __restrict__ wS1, const float* __restrict__ wS2,
           float* __restrict__ out)
{
    constexpr int Kd = FUSED ? H_ : I_;
    constexpr int Nd = FUSED ? I_ : H_;
    constexpr int C  = Kd / 32;
    constexpr int NO = FUSED ? 2 : 1;   // outputs (gate,up) vs one
    constexpr int NT = FUSED ? 2 : 4;   // n-subtiles of 8 per warp per output

    const int e = blockIdx.z;
    const bool sh = (e == E_);
    const int M = sh ? T_ : min(d_cnt[e], CAP_);
    const int m0 = blockIdx.y * 128;
    if (m0 >= M) return;
    const int n0 = blockIdx.x * (FUSED ? 64 : 128);

    const float* Asrc; const float* B1; const float* B2 = nullptr; float* Cp;
    if (FUSED) {
        Asrc = x;
        B1 = sh ? wS1 : wR1 + (size_t)e * Nd * Kd;
        B2 = sh ? wS2 : wR2 + (size_t)e * Nd * Kd;
        Cp = sh ? d_sinter : d_inter + (size_t)e * CAP_ * Nd;
    } else {
        Asrc = sh ? d_sinter : d_inter + (size_t)e * CAP_ * Kd;
        B1 = sh ? wS1 : wR1 + (size_t)e * Nd * Kd;
        Cp = sh ? out : d_yb + (size_t)e * CAP_ * Nd;
    }

    __shared__ int srow[128];
    extern __shared__ char dsm[];
    const int tid = threadIdx.x;
    const int wid = tid >> 5, lane = tid & 31;
    const int wr = wid >> 2, wc = wid & 3;     // 2 x 4 warp grid
    const int g = lane >> 2, tig = lane & 3;

    const bool gath = FUSED && !sh;
    if (gath && tid < 128) srow[tid] = (m0 + tid < M) ? d_src[e * CAP_ + m0 + tid] : 0;
    __syncthreads();

    // ---- per-thread loader geometry (constant across chunks) ----
    const int c4   = tid & 7;        // which 4-float group in the 32-k chunk
    const int ksl  = c4 >> 1;        // k-subblock 0..3
    const int hlf  = c4 & 1;         // k half (0: k<4, 1: k>=4 within subblock)
    const int r0l  = tid >> 3;       // base row (rows r0l + 32q)
    const int gA   = r0l & 7;
    const int hiA  = (r0l >> 3) & 1;
    const int mb0  = r0l >> 4;
    const int cb0  = r0l >> 3;
    // A sts base for q=0 (float index), +1056 per q
    const int stA0 = (mb0 * 4 + ksl) * 132 + gA * 16 + hiA + 2 * hlf;
    // B sts base for q=0, +1056 per q
    const int stB0 = (cb0 * 4 + ksl) * 66 + gA * 8 + hlf;

    float4 ra[4], rb[4];
    bool va[4];

    auto ldg_chunk = [&](int kt) {
        #pragma unroll
        for (int q = 0; q < 4; q++) {
            int row = r0l + 32 * q;
            // A row
            bool v = (m0 + row) < M;
            va[q] = v;
            const float* gp;
            if (gath) gp = x + (size_t)srow[row] * Kd + kt + c4 * 4;
            else      gp = Asrc + (size_t)(v ? (m0 + row) : m0) * Kd + kt + c4 * 4;
            ra[q] = v ? *(const float4*)gp : make_float4(0.f, 0.f, 0.f, 0.f);
            // B row (for FUSED rows 0..63 -> Bg, 64..127 -> Bu)
            const float* gb;
            if (FUSED) gb = (row < 64 ? B1 + (size_t)(n0 + row) * Kd
                                      : B2 + (size_t)(n0 + row - 64) * Kd) + kt + c4 * 4;
            else       gb = B1 + (size_t)(n0 + row) * Kd + kt + c4 * 4;
            rb[q] = *(const float4*)gb;
        }
    };
    auto sts_chunk = [&](int s) {
        float* As = (float*)(dsm + (size_t)s * STG_BYTES);
        float* Bs = As + A_FLOATS;
        #pragma unroll
        for (int q = 0; q < 4; q++) {
            int a0 = stA0 + 1056 * q;
            As[a0 + 0]  = tf32f(ra[q].x);
            As[a0 + 4]  = tf32f(ra[q].y);
            As[a0 + 8]  = tf32f(ra[q].z);
            As[a0 + 12] = tf32f(ra[q].w);
            int b0 = stB0 + 1056 * q;
            Bs[b0 + 0] = tf32f(rb[q].x);
            Bs[b0 + 2] = tf32f(rb[q].y);
            Bs[b0 + 4] = tf32f(rb[q].z);
            Bs[b0 + 6] = tf32f(rb[q].w);
        }
    };

    float acc[NO][4][NT][4];
    #pragma unroll
    for (int o = 0; o < NO; o++)
        #pragma unroll
        for (int mt = 0; mt < 4; mt++)
            #pragma unroll
            for (int nt = 0; nt < NT; nt++)
                #pragma unroll
                for (int r = 0; r < 4; r++) acc[o][mt][nt][r] = 0.f;

    ldg_chunk(0);

    for (int c = 0; c < C; c++) {
        const int s = c & 1;
        sts_chunk(s);
        __syncthreads();
        if (c + 1 < C) ldg_chunk((c + 1) * 32);

        const float* As = (const float*)(dsm + (size_t)s * STG_BYTES);
        const float* Bs = As + A_FLOATS;
        #pragma unroll
        for (int ks = 0; ks < 4; ks++) {
            uint32_t a[4][4];
            #pragma unroll
            for (int mt = 0; mt < 4; mt++) {
                float4 v = *(const float4*)(As + ((wr * 4 + mt) * 4 + ks) * 132 + lane * 4);
                a[mt][0] = __float_as_uint(v.x); a[mt][1] = __float_as_uint(v.y);
                a[mt][2] = __float_as_uint(v.z); a[mt][3] = __float_as_uint(v.w);
            }
            uint32_t b[NO][NT][2];
            #pragma unroll
            for (int o = 0; o < NO; o++)
                #pragma unroll
                for (int nt = 0; nt < NT; nt++) {
                    int cb = FUSED ? (o * 8 + wc * 2 + nt) : (wc * 4 + nt);
                    float2 v = *(const float2*)(Bs + (cb * 4 + ks) * 66 + lane * 2);
                    b[o][nt][0] = __float_as_uint(v.x);
                    b[o][nt][1] = __float_as_uint(v.y);
                }
            #pragma unroll
            for (int o = 0; o < NO; o++)
                #pragma unroll
                for (int mt = 0; mt < 4; mt++)
                    #pragma unroll
                    for (int nt = 0; nt < NT; nt++)
                        mma_tf32(acc[o][mt][nt], a[mt], b[o][nt]);
        }
        __syncthreads();
    }

    // ---- epilogue ----
    #pragma unroll
    for (int mt = 0; mt < 4; mt++) {
        #pragma unroll
        for (int nt = 0; nt < NT; nt++) {
            int r0 = m0 + wr * 64 + mt * 16 + g;
            int col = n0 + wc * (FUSED ? 16 : 32) + nt * 8 + 2 * tig;
            #pragma unroll
            for (int h = 0; h < 2; h++) {
                int r = r0 + 8 * h;
                if (r >= M) continue;
                if (FUSED) {
                    float gg0 = acc[0][mt][nt][2 * h + 0];
                    float gg1 = acc[0][mt][nt][2 * h + 1];
                    float uu0 = acc[1][mt][nt][2 * h + 0];
                    float uu1 = acc[1][mt][nt][2 * h + 1];
                    float s0 = gg0 / (1.f + expf(-gg0)) * uu0;
                    float s1 = gg1 / (1.f + expf(-gg1)) * uu1;
                    if (sh) {
                        s0 = fminf(fmaxf(s0, -10.f), 10.f);
                        s1 = fminf(fmaxf(s1, -10.f), 10.f);
                    }
                    *(float2*)(Cp + (size_t)r * Nd + col) = make_float2(s0, s1);
                } else {
                    *(float2*)(Cp + (size_t)r * Nd + col) =
                        make_float2(acc[0][mt][nt][2 * h + 0], acc[0][mt][nt][2 * h + 1]);
                }
            }
        }
    }
}

// ---------------- combine: out[t] = shared(out) + sum_k w * yb[slot] ----------------
__global__ void combine_kernel(float* __restrict__ out) {
    int t = blockIdx.x;
    __shared__ int   ss[TOPK];
    __shared__ float sw[TOPK];
    if (threadIdx.x < TOPK) {
        ss[threadIdx.x] = d_slot[t * TOPK + threadIdx.x];
        sw[threadIdx.x] = d_wt[t * TOPK + threadIdx.x];
    }
    __syncthreads();
    float4* orow = (float4*)(out + (size_t)t * H_);
    for (int i = threadIdx.x; i < H_ / 4; i += blockDim.x) {
        float4 o = orow[i];
        #pragma unroll
        for (int k = 0; k < TOPK; k++) {
            int slot = ss[k];
            if (slot < 0) continue;
            float w = sw[k];
            float4 y = ((const float4*)(d_yb + (size_t)slot * H_))[i];
            o.x += w * y.x; o.y += w * y.y; o.z += w * y.z; o.w += w * y.w;
        }
        orow[i] = o;
    }
}

// ---------------- launch ----------------
extern "C" void kernel_launch(void* const* d_in, const int* in_sizes, int n_in,
                              void* d_out, int out_size) {
    const float* x      = (const float*)d_in[0];
    const float* gate_w = (const float*)d_in[1];
    const float* bias   = (const float*)d_in[2];
    const float* w_gate = (const float*)d_in[3];
    const float* w_up   = (const float*)d_in[4];
    const float* w_down = (const float*)d_in[5];
    const float* sg     = (const float*)d_in[6];
    const float* su     = (const float*)d_in[7];
    const float* sd     = (const float*)d_in[8];
    float* out = (float*)d_out;

    cudaFuncSetAttribute(gemm2<true>,  cudaFuncAttributeMaxDynamicSharedMemorySize, SMEM_G2);
    cudaFuncSetAttribute(gemm2<false>, cudaFuncAttributeMaxDynamicSharedMemorySize, SMEM_G2);

    init_kernel<<<1, 32>>>();
    router_kernel<<<T_, 128>>>(x, gate_w, bias);

    // fused gate+up (SwiGLU) then down — routed e=0..31 + shared e=32
    gemm2<true><<<dim3(I_ / 64, T_ / 128, E_ + 1), 256, SMEM_G2>>>(x, w_gate, w_up, sg, su, nullptr);
    gemm2<false><<<dim3(H_ / 128, T_ / 128, E_ + 1), 256, SMEM_G2>>>(nullptr, w_down, nullptr, sd, nullptr, out);

    combine_kernel<<<T_, 256>>>(out);
}

// round 11
// speedup vs baseline: 1.2493x; 1.2493x over previous
#include <cuda_runtime.h>
#include <math.h>
#include <stdint.h>

#define E_    32
#define TOPK  6
#define H_    2048
#define I_    1024
#define T_    2048
#define CAP_  768
#define SCALE_ 1.5f

// ---------------- scratch (device globals; no allocation allowed) ----------------
__device__ int   d_cnt[E_];
__device__ int   d_src[E_ * CAP_];        // slot -> token
__device__ int   d_slot[T_ * TOPK];       // e*CAP_+pos, or -1 if dropped
__device__ float d_wt[T_ * TOPK];         // normalized * SCALE_
__device__ float d_inter[(size_t)E_ * CAP_ * I_];   // silu(g)*u per expert
__device__ float d_sinter[(size_t)T_ * I_];         // shared-expert intermediate
__device__ float d_yb[(size_t)E_ * CAP_ * H_];      // expert outputs

// =================== portable PTX helpers (compute_103-safe, sm_80+) ===================
__device__ __forceinline__ uint32_t smem_u32(const void* p) {
    uint32_t a;
    asm("{ .reg .u64 t; cvta.to.shared.u64 t, %1; cvt.u32.u64 %0, t; }" : "=r"(a) : "l"(p));
    return a;
}
__device__ __forceinline__ uint32_t tf32r(float f) {
    uint32_t r; asm("cvt.rna.tf32.f32 %0, %1;" : "=r"(r) : "f"(f)); return r;
}
__device__ __forceinline__ void cp16(uint32_t saddr, const void* gaddr, bool v) {
    int sz = v ? 16 : 0;
    asm volatile("cp.async.ca.shared.global [%0], [%1], 16, %2;"
                 :: "r"(saddr), "l"(gaddr), "r"(sz) : "memory");
}
#define CP_COMMIT() asm volatile("cp.async.commit_group;" ::: "memory")
#define CP_WAIT1()  asm volatile("cp.async.wait_group 1;" ::: "memory")
#define CP_WAIT0()  asm volatile("cp.async.wait_group 0;" ::: "memory")

__device__ __forceinline__ void mma_tf32(float* c, const uint32_t* a, const uint32_t* b) {
    asm volatile(
        "mma.sync.aligned.m16n8k8.row.col.f32.tf32.tf32.f32 "
        "{%0,%1,%2,%3}, {%4,%5,%6,%7}, {%8,%9}, {%0,%1,%2,%3};"
        : "+f"(c[0]), "+f"(c[1]), "+f"(c[2]), "+f"(c[3])
        : "r"(a[0]), "r"(a[1]), "r"(a[2]), "r"(a[3]), "r"(b[0]), "r"(b[1]));
}

// ---------------- init ----------------
__global__ void init_kernel() {
    if (threadIdx.x < E_) d_cnt[threadIdx.x] = 0;
}

// ---------------- router ----------------
__global__ void router_kernel(const float* __restrict__ x,
                              const float* __restrict__ gw,
                              const float* __restrict__ bias) {
    int t = blockIdx.x;
    const float4* h4 = (const float4*)(x + (size_t)t * H_);
    __shared__ float sc[E_];
    __shared__ float sb[E_];
    int warp = threadIdx.x >> 5, lane = threadIdx.x & 31;

    for (int e = warp; e < E_; e += 4) {
        const float4* w4 = (const float4*)(gw + (size_t)e * H_);
        float s = 0.f;
        for (int i = lane; i < H_ / 4; i += 32) {
            float4 a = h4[i], b = w4[i];
            s += a.x * b.x + a.y * b.y + a.z * b.z + a.w * b.w;
        }
        #pragma unroll
        for (int o = 16; o > 0; o >>= 1) s += __shfl_xor_sync(0xffffffffu, s, o);
        if (lane == 0) {
            float sp = (s > 15.f) ? s : log1pf(expf(s));
            sc[e] = sqrtf(sp);
        }
    }
    __syncthreads();
    if (threadIdx.x < E_) sb[threadIdx.x] = sc[threadIdx.x] + bias[threadIdx.x];
    __syncthreads();

    if (threadIdx.x == 0) {
        int   idx[TOPK];
        float wsum = 0.f;
        for (int k = 0; k < TOPK; k++) {
            int best = 0; float bv = -1e30f;
            for (int e = 0; e < E_; e++)
                if (sb[e] > bv) { bv = sb[e]; best = e; }
            idx[k] = best;
            sb[best] = -1e30f;
            wsum += sc[best];
        }
        float inv = SCALE_ / wsum;
        for (int k = 0; k < TOPK; k++) {
            int e = idx[k];
            int pos = atomicAdd(&d_cnt[e], 1);
            if (pos < CAP_) {
                d_slot[t * TOPK + k] = e * CAP_ + pos;
                d_src[e * CAP_ + pos] = t;
            } else {
                d_slot[t * TOPK + k] = -1;
            }
            d_wt[t * TOPK + k] = sc[e] * inv;
        }
    }
}

// =================== tf32 mma.sync GEMM (R5 engine + fused gate/up) ===================
// FUSED=1: CTA computes G,U [128 x 64] = A[128,K=2048] @ {Bg,Bu}^T, SwiGLU -> d_inter/d_sinter
//          B smem tile rows 0..63 = Bg rows, 64..127 = Bu rows.
// FUSED=0: CTA computes C [128 x 128] = A[128,K=1024] @ B^T (down) -> d_yb / out
// 8 warps (2m x 4n). FUSED warp tile 64x16 per output; down warp tile 64x32.
// smem: [row][k] pitch 36 floats, double-buffered, cp.async-fed (no staging regs).

#define PITCH 36
#define STAGE_FLOATS (128 * PITCH)            // 4608 per operand
#define STAGE_BYTES  (2 * STAGE_FLOATS * 4)   // 36864 (A + B)
#define SMEM_GEMM    (2 * STAGE_BYTES)        // 73728 -> 2 CTAs/SM

template<bool FUSED>
__global__ __launch_bounds__(256, 2)
void gemm_tc(const float* __restrict__ x,
             const float* __restrict__ wR1, const float* __restrict__ wR2,
             const float* __restrict__ wS1, const float* __restrict__ wS2,
             float* __restrict__ out)
{
    constexpr int Kd = FUSED ? H_ : I_;
    constexpr int Nd = FUSED ? I_ : H_;
    constexpr int C  = Kd / 32;
    constexpr int NO = FUSED ? 2 : 1;
    constexpr int NT = FUSED ? 2 : 4;

    const int e = blockIdx.z;
    const bool sh = (e == E_);
    const int M = sh ? T_ : min(d_cnt[e], CAP_);
    const int m0 = blockIdx.y * 128;
    if (m0 >= M) return;
    const int n0 = blockIdx.x * (FUSED ? 64 : 128);

    const float* Asrc; const float* B1; const float* B2 = nullptr; float* Cp;
    if (FUSED) {
        Asrc = x;
        B1 = sh ? wS1 : wR1 + (size_t)e * Nd * Kd;   // gate
        B2 = sh ? wS2 : wR2 + (size_t)e * Nd * Kd;   // up
        Cp = sh ? d_sinter : d_inter + (size_t)e * CAP_ * Nd;
    } else {
        Asrc = sh ? d_sinter : d_inter + (size_t)e * CAP_ * Kd;
        B1 = sh ? wS1 : wR1 + (size_t)e * Nd * Kd;
        Cp = sh ? out : d_yb + (size_t)e * CAP_ * Nd;
    }

    extern __shared__ char dsm[];
    __shared__ int srow[128];

    const int tid = threadIdx.x;
    const int wid = tid >> 5, lane = tid & 31;
    const int wr = wid >> 2, wc = wid & 3;       // warp 2x4 grid
    const int g = lane >> 2, tig = lane & 3;

    const bool gath = FUSED && !sh;
    if (gath && tid < 128) srow[tid] = (m0 + tid < M) ? d_src[e * CAP_ + m0 + tid] : 0;
    __syncthreads();

    const uint32_t smem_base = smem_u32(dsm);

    // ---- chunk loader: A and B tiles (128 rows x 32 k) via cp.async ----
    auto load_chunk = [&](int kt, int s) {
        const uint32_t sa = smem_base + (uint32_t)s * STAGE_BYTES;
        const uint32_t sbB = sa + STAGE_FLOATS * 4;
        #pragma unroll
        for (int q = 0; q < 4; q++) {
            int idx = tid + q * 256;
            int row = idx >> 3, c4 = idx & 7;
            // A
            int gr = m0 + row;
            bool v = gr < M;
            const float* gp;
            if (gath) gp = x + (size_t)srow[row] * Kd + kt + c4 * 4;
            else      gp = Asrc + (size_t)(v ? gr : m0) * Kd + kt + c4 * 4;
            cp16(sa + (uint32_t)(row * PITCH + c4 * 4) * 4, gp, v);
            // B (FUSED: rows 0..63 gate, 64..127 up)
            const float* gb;
            if (FUSED) gb = (row < 64 ? B1 + (size_t)(n0 + row) * Kd
                                      : B2 + (size_t)(n0 + row - 64) * Kd) + kt + c4 * 4;
            else       gb = B1 + (size_t)(n0 + row) * Kd + kt + c4 * 4;
            cp16(sbB + (uint32_t)(row * PITCH + c4 * 4) * 4, gb, true);
        }
    };

    float acc[NO][4][NT][4];
    #pragma unroll
    for (int o = 0; o < NO; o++)
        #pragma unroll
        for (int mt = 0; mt < 4; mt++)
            #pragma unroll
            for (int nt = 0; nt < NT; nt++)
                #pragma unroll
                for (int r = 0; r < 4; r++) acc[o][mt][nt][r] = 0.f;

    load_chunk(0, 0);
    CP_COMMIT();

    for (int c = 0; c < C; c++) {
        const int s = c & 1;
        if (c + 1 < C) { load_chunk((c + 1) * 32, s ^ 1); CP_COMMIT(); CP_WAIT1(); }
        else           { CP_WAIT0(); }
        __syncthreads();

        const float* As = (const float*)(dsm + (size_t)s * STAGE_BYTES);
        const float* Bs = As + STAGE_FLOATS;
        #pragma unroll
        for (int ks = 0; ks < 4; ks++) {
            uint32_t a[4][4];
            #pragma unroll
            for (int mt = 0; mt < 4; mt++) {
                int base = (wr * 64 + mt * 16 + g) * PITCH + ks * 8 + tig;
                a[mt][0] = tf32r(As[base]);
                a[mt][1] = tf32r(As[base + 8 * PITCH]);
                a[mt][2] = tf32r(As[base + 4]);
                a[mt][3] = tf32r(As[base + 8 * PITCH + 4]);
            }
            uint32_t b[NO][NT][2];
            #pragma unroll
            for (int o = 0; o < NO; o++)
                #pragma unroll
                for (int nt = 0; nt < NT; nt++) {
                    int brow = FUSED ? (o * 64 + wc * 16 + nt * 8 + g)
                                     : (wc * 32 + nt * 8 + g);
                    int base = brow * PITCH + ks * 8 + tig;
                    b[o][nt][0] = tf32r(Bs[base]);
                    b[o][nt][1] = tf32r(Bs[base + 4]);
                }
            #pragma unroll
            for (int o = 0; o < NO; o++)
                #pragma unroll
                for (int mt = 0; mt < 4; mt++)
                    #pragma unroll
                    for (int nt = 0; nt < NT; nt++)
                        mma_tf32(acc[o][mt][nt], a[mt], b[o][nt]);
        }
        __syncthreads();
    }

    // ---- epilogue ----
    #pragma unroll
    for (int mt = 0; mt < 4; mt++) {
        #pragma unroll
        for (int nt = 0; nt < NT; nt++) {
            int r0 = m0 + wr * 64 + mt * 16 + g;
            int col = n0 + wc * (FUSED ? 16 : 32) + nt * 8 + 2 * tig;
            #pragma unroll
            for (int h = 0; h < 2; h++) {
                int r = r0 + 8 * h;
                if (r >= M) continue;
                if (FUSED) {
                    float gg0 = acc[0][mt][nt][2 * h + 0];
                    float gg1 = acc[0][mt][nt][2 * h + 1];
                    float uu0 = acc[1][mt][nt][2 * h + 0];
                    float uu1 = acc[1][mt][nt][2 * h + 1];
                    float s0 = gg0 / (1.f + expf(-gg0)) * uu0;
                    float s1 = gg1 / (1.f + expf(-gg1)) * uu1;
                    if (sh) {
                        s0 = fminf(fmaxf(s0, -10.f), 10.f);
                        s1 = fminf(fmaxf(s1, -10.f), 10.f);
                    }
                    *(float2*)(Cp + (size_t)r * Nd + col) = make_float2(s0, s1);
                } else {
                    *(float2*)(Cp + (size_t)r * Nd + col) =
                        make_float2(acc[0][mt][nt][2 * h + 0], acc[0][mt][nt][2 * h + 1]);
                }
            }
        }
    }
}

// ---------------- combine: out[t] = shared(out) + sum_k w * yb[slot] ----------------
__global__ void combine_kernel(float* __restrict__ out) {
    int t = blockIdx.x;
    __shared__ int   ss[TOPK];
    __shared__ float sw[TOPK];
    if (threadIdx.x < TOPK) {
        ss[threadIdx.x] = d_slot[t * TOPK + threadIdx.x];
        sw[threadIdx.x] = d_wt[t * TOPK + threadIdx.x];
    }
    __syncthreads();
    float4* orow = (float4*)(out + (size_t)t * H_);
    for (int i = threadIdx.x; i < H_ / 4; i += blockDim.x) {
        float4 o = orow[i];
        #pragma unroll
        for (int k = 0; k < TOPK; k++) {
            int slot = ss[k];
            if (slot < 0) continue;
            float w = sw[k];
            float4 y = ((const float4*)(d_yb + (size_t)slot * H_))[i];
            o.x += w * y.x; o.y += w * y.y; o.z += w * y.z; o.w += w * y.w;
        }
        orow[i] = o;
    }
}

// ---------------- launch ----------------
extern "C" void kernel_launch(void* const* d_in, const int* in_sizes, int n_in,
                              void* d_out, int out_size) {
    const float* x      = (const float*)d_in[0];
    const float* gate_w = (const float*)d_in[1];
    const float* bias   = (const float*)d_in[2];
    const float* w_gate = (const float*)d_in[3];
    const float* w_up   = (const float*)d_in[4];
    const float* w_down = (const float*)d_in[5];
    const float* sg     = (const float*)d_in[6];
    const float* su     = (const float*)d_in[7];
    const float* sd     = (const float*)d_in[8];
    float* out = (float*)d_out;

    cudaFuncSetAttribute(gemm_tc<true>,  cudaFuncAttributeMaxDynamicSharedMemorySize, SMEM_GEMM);
    cudaFuncSetAttribute(gemm_tc<false>, cudaFuncAttributeMaxDynamicSharedMemorySize, SMEM_GEMM);

    init_kernel<<<1, 32>>>();
    router_kernel<<<T_, 128>>>(x, gate_w, bias);

    // fused gate+up (SwiGLU), then down — routed e=0..31 + shared e=32
    gemm_tc<true><<<dim3(I_ / 64, T_ / 128, E_ + 1), 256, SMEM_GEMM>>>(x, w_gate, w_up, sg, su, nullptr);
    gemm_tc<false><<<dim3(H_ / 128, T_ / 128, E_ + 1), 256, SMEM_GEMM>>>(nullptr, w_down, nullptr, sd, nullptr, out);

    combine_kernel<<<T_, 256>>>(out);
}

// round 13
// speedup vs baseline: 1.3128x; 1.0508x over previous
#include <cuda_runtime.h>
#include <math.h>
#include <stdint.h>

#define E_    32
#define TOPK  6
#define H_    2048
#define I_    1024
#define T_    2048
#define CAP_  768
#define SCALE_ 1.5f

// ---------------- scratch (device globals; no allocation allowed) ----------------
__device__ int   d_cnt[E_];
__device__ int   d_src[E_ * CAP_];        // slot -> token
__device__ int   d_slot[T_ * TOPK];       // e*CAP_+pos, or -1 if dropped
__device__ float d_wt[T_ * TOPK];         // normalized * SCALE_
__device__ float d_xr[(size_t)T_ * H_];             // tf32-rounded x (GEMM A operand)
__device__ float d_inter[(size_t)E_ * CAP_ * I_];   // silu(g)*u per expert (tf32-rounded)
__device__ float d_sinter[(size_t)T_ * I_];         // shared-expert intermediate (tf32-rounded)
__device__ float d_yb[(size_t)E_ * CAP_ * H_];      // expert outputs (f32)

// =================== portable PTX helpers (compute_103-safe, sm_80+) ===================
__device__ __forceinline__ uint32_t smem_u32(const void* p) {
    uint32_t a;
    asm("{ .reg .u64 t; cvta.to.shared.u64 t, %1; cvt.u32.u64 %0, t; }" : "=r"(a) : "l"(p));
    return a;
}
__device__ __forceinline__ uint32_t tf32r(float f) {
    uint32_t r; asm("cvt.rna.tf32.f32 %0, %1;" : "=r"(r) : "f"(f)); return r;
}
__device__ __forceinline__ float tf32f(float f) {
    return __uint_as_float(tf32r(f));
}
__device__ __forceinline__ void cp16(uint32_t saddr, const void* gaddr, bool v) {
    int sz = v ? 16 : 0;
    asm volatile("cp.async.ca.shared.global [%0], [%1], 16, %2;"
                 :: "r"(saddr), "l"(gaddr), "r"(sz) : "memory");
}
#define CP_COMMIT() asm volatile("cp.async.commit_group;" ::: "memory")
#define CP_WAIT1()  asm volatile("cp.async.wait_group 1;" ::: "memory")
#define CP_WAIT0()  asm volatile("cp.async.wait_group 0;" ::: "memory")

__device__ __forceinline__ void mma_tf32(float* c, const uint32_t* a, const uint32_t* b) {
    asm volatile(
        "mma.sync.aligned.m16n8k8.row.col.f32.tf32.tf32.f32 "
        "{%0,%1,%2,%3}, {%4,%5,%6,%7}, {%8,%9}, {%0,%1,%2,%3};"
        : "+f"(c[0]), "+f"(c[1]), "+f"(c[2]), "+f"(c[3])
        : "r"(a[0]), "r"(a[1]), "r"(a[2]), "r"(a[3]), "r"(b[0]), "r"(b[1]));
}

// ---------------- init ----------------
__global__ void init_kernel() {
    if (threadIdx.x < E_) d_cnt[threadIdx.x] = 0;
}

// ---------------- pre-round x to tf32 (A operand) ----------------
__global__ void round_x_kernel(const float* __restrict__ x) {
    int i = blockIdx.x * blockDim.x + threadIdx.x;   // over float4s
    float4 v = ((const float4*)x)[i];
    float4 o = make_float4(tf32f(v.x), tf32f(v.y), tf32f(v.z), tf32f(v.w));
    ((float4*)d_xr)[i] = o;
}

// ---------------- router ----------------
__global__ void router_kernel(const float* __restrict__ x,
                              const float* __restrict__ gw,
                              const float* __restrict__ bias) {
    int t = blockIdx.x;
    const float4* h4 = (const float4*)(x + (size_t)t * H_);
    __shared__ float sc[E_];
    __shared__ float sb[E_];
    int warp = threadIdx.x >> 5, lane = threadIdx.x & 31;

    for (int e = warp; e < E_; e += 4) {
        const float4* w4 = (const float4*)(gw + (size_t)e * H_);
        float s = 0.f;
        for (int i = lane; i < H_ / 4; i += 32) {
            float4 a = h4[i], b = w4[i];
            s += a.x * b.x + a.y * b.y + a.z * b.z + a.w * b.w;
        }
        #pragma unroll
        for (int o = 16; o > 0; o >>= 1) s += __shfl_xor_sync(0xffffffffu, s, o);
        if (lane == 0) {
            float sp = (s > 15.f) ? s : log1pf(expf(s));
            sc[e] = sqrtf(sp);
        }
    }
    __syncthreads();
    if (threadIdx.x < E_) sb[threadIdx.x] = sc[threadIdx.x] + bias[threadIdx.x];
    __syncthreads();

    if (threadIdx.x == 0) {
        int   idx[TOPK];
        float wsum = 0.f;
        for (int k = 0; k < TOPK; k++) {
            int best = 0; float bv = -1e30f;
            for (int e = 0; e < E_; e++)
                if (sb[e] > bv) { bv = sb[e]; best = e; }
            idx[k] = best;
            sb[best] = -1e30f;
            wsum += sc[best];
        }
        float inv = SCALE_ / wsum;
        for (int k = 0; k < TOPK; k++) {
            int e = idx[k];
            int pos = atomicAdd(&d_cnt[e], 1);
            if (pos < CAP_) {
                d_slot[t * TOPK + k] = e * CAP_ + pos;
                d_src[e * CAP_ + pos] = t;
            } else {
                d_slot[t * TOPK + k] = -1;
            }
            d_wt[t * TOPK + k] = sc[e] * inv;
        }
    }
}

// =================== tf32 mma.sync GEMM (pre-rounded A: no cvt on A path) ===================
// FUSED=1: CTA computes G,U [128 x 64] = A[128,K=2048] @ {Bg,Bu}^T, SwiGLU -> d_inter/d_sinter
//          A = d_xr (pre-rounded). B smem rows 0..63 = Bg, 64..127 = Bu.
// FUSED=0: CTA computes C [128 x 128] = A[128,K=1024] @ B^T (down) -> d_yb / out
//          A = d_inter/d_sinter (stored pre-rounded by gateup epilogue).
// 8 warps (2m x 4n). smem [row][k] pitch 36 floats, double-buffered, cp.async-fed.

#define PITCH 36
#define STAGE_FLOATS (128 * PITCH)            // 4608 per operand
#define STAGE_BYTES  (2 * STAGE_FLOATS * 4)   // 36864 (A + B)
#define SMEM_GEMM    (2 * STAGE_BYTES)        // 73728 -> 2 CTAs/SM

template<bool FUSED>
__global__ __launch_bounds__(256, 2)
void gemm_tc(const float* __restrict__ wR1, const float* __restrict__ wR2,
             const float* __restrict__ wS1, const float* __restrict__ wS2,
             float* __restrict__ out)
{
    constexpr int Kd = FUSED ? H_ : I_;
    constexpr int Nd = FUSED ? I_ : H_;
    constexpr int C  = Kd / 32;
    constexpr int NO = FUSED ? 2 : 1;
    constexpr int NT = FUSED ? 2 : 4;

    const int e = blockIdx.z;
    const bool sh = (e == E_);
    const int M = sh ? T_ : min(d_cnt[e], CAP_);
    const int m0 = blockIdx.y * 128;
    if (m0 >= M) return;
    const int n0 = blockIdx.x * (FUSED ? 64 : 128);

    const float* Asrc; const float* B1; const float* B2 = nullptr; float* Cp;
    if (FUSED) {
        Asrc = d_xr;
        B1 = sh ? wS1 : wR1 + (size_t)e * Nd * Kd;   // gate
        B2 = sh ? wS2 : wR2 + (size_t)e * Nd * Kd;   // up
        Cp = sh ? d_sinter : d_inter + (size_t)e * CAP_ * Nd;
    } else {
        Asrc = sh ? d_sinter : d_inter + (size_t)e * CAP_ * Kd;
        B1 = sh ? wS1 : wR1 + (size_t)e * Nd * Kd;
        Cp = sh ? out : d_yb + (size_t)e * CAP_ * Nd;
    }

    extern __shared__ char dsm[];
    __shared__ int srow[128];

    const int tid = threadIdx.x;
    const int wid = tid >> 5, lane = tid & 31;
    const int wr = wid >> 2, wc = wid & 3;       // warp 2x4 grid
    const int g = lane >> 2, tig = lane & 3;

    const bool gath = FUSED && !sh;
    if (gath && tid < 128) srow[tid] = (m0 + tid < M) ? d_src[e * CAP_ + m0 + tid] : 0;
    __syncthreads();

    const uint32_t smem_base = smem_u32(dsm);

    // ---- chunk loader: A and B tiles (128 rows x 32 k) via cp.async ----
    auto load_chunk = [&](int kt, int s) {
        const uint32_t sa = smem_base + (uint32_t)s * STAGE_BYTES;
        const uint32_t sbB = sa + STAGE_FLOATS * 4;
        #pragma unroll
        for (int q = 0; q < 4; q++) {
            int idx = tid + q * 256;
            int row = idx >> 3, c4 = idx & 7;
            // A
            int gr = m0 + row;
            bool v = gr < M;
            const float* gp;
            if (gath) gp = Asrc + (size_t)srow[row] * Kd + kt + c4 * 4;
            else      gp = Asrc + (size_t)(v ? gr : m0) * Kd + kt + c4 * 4;
            cp16(sa + (uint32_t)(row * PITCH + c4 * 4) * 4, gp, v);
            // B (FUSED: rows 0..63 gate, 64..127 up)
            const float* gb;
            if (FUSED) gb = (row < 64 ? B1 + (size_t)(n0 + row) * Kd
                                      : B2 + (size_t)(n0 + row - 64) * Kd) + kt + c4 * 4;
            else       gb = B1 + (size_t)(n0 + row) * Kd + kt + c4 * 4;
            cp16(sbB + (uint32_t)(row * PITCH + c4 * 4) * 4, gb, true);
        }
    };

    float acc[NO][4][NT][4];
    #pragma unroll
    for (int o = 0; o < NO; o++)
        #pragma unroll
        for (int mt = 0; mt < 4; mt++)
            #pragma unroll
            for (int nt = 0; nt < NT; nt++)
                #pragma unroll
                for (int r = 0; r < 4; r++) acc[o][mt][nt][r] = 0.f;

    load_chunk(0, 0);
    CP_COMMIT();

    for (int c = 0; c < C; c++) {
        const int s = c & 1;
        if (c + 1 < C) { load_chunk((c + 1) * 32, s ^ 1); CP_COMMIT(); CP_WAIT1(); }
        else           { CP_WAIT0(); }
        __syncthreads();

        const float* As = (const float*)(dsm + (size_t)s * STAGE_BYTES);
        const float* Bs = As + STAGE_FLOATS;
        #pragma unroll
        for (int ks = 0; ks < 4; ks++) {
            uint32_t a[4][4];
            #pragma unroll
            for (int mt = 0; mt < 4; mt++) {
                int base = (wr * 64 + mt * 16 + g) * PITCH + ks * 8 + tig;
                // A is pre-rounded tf32: raw bit loads, no cvt
                a[mt][0] = __float_as_uint(As[base]);
                a[mt][1] = __float_as_uint(As[base + 8 * PITCH]);
                a[mt][2] = __float_as_uint(As[base + 4]);
                a[mt][3] = __float_as_uint(As[base + 8 * PITCH + 4]);
            }
            uint32_t b[NO][NT][2];
            #pragma unroll
            for (int o = 0; o < NO; o++)
                #pragma unroll
                for (int nt = 0; nt < NT; nt++) {
                    int brow = FUSED ? (o * 64 + wc * 16 + nt * 8 + g)
                                     : (wc * 32 + nt * 8 + g);
                    int base = brow * PITCH + ks * 8 + tig;
                    b[o][nt][0] = tf32r(Bs[base]);
                    b[o][nt][1] = tf32r(Bs[base + 4]);
                }
            #pragma unroll
            for (int o = 0; o < NO; o++)
                #pragma unroll
                for (int mt = 0; mt < 4; mt++)
                    #pragma unroll
                    for (int nt = 0; nt < NT; nt++)
                        mma_tf32(acc[o][mt][nt], a[mt], b[o][nt]);
        }
        __syncthreads();
    }

    // ---- epilogue ----
    #pragma unroll
    for (int mt = 0; mt < 4; mt++) {
        #pragma unroll
        for (int nt = 0; nt < NT; nt++) {
            int r0 = m0 + wr * 64 + mt * 16 + g;
            int col = n0 + wc * (FUSED ? 16 : 32) + nt * 8 + 2 * tig;
            #pragma unroll
            for (int h = 0; h < 2; h++) {
                int r = r0 + 8 * h;
                if (r >= M) continue;
                if (FUSED) {
                    float gg0 = acc[0][mt][nt][2 * h + 0];
                    float gg1 = acc[0][mt][nt][2 * h + 1];
                    float uu0 = acc[1][mt][nt][2 * h + 0];
                    float uu1 = acc[1][mt][nt][2 * h + 1];
                    float s0 = gg0 / (1.f + expf(-gg0)) * uu0;
                    float s1 = gg1 / (1.f + expf(-gg1)) * uu1;
                    if (sh) {
                        s0 = fminf(fmaxf(s0, -10.f), 10.f);
                        s1 = fminf(fmaxf(s1, -10.f), 10.f);
                    }
                    // store pre-rounded: down pass reads A without cvt (numerically identical)
                    *(float2*)(Cp + (size_t)r * Nd + col) = make_float2(tf32f(s0), tf32f(s1));
                } else {
                    *(float2*)(Cp + (size_t)r * Nd + col) =
                        make_float2(acc[0][mt][nt][2 * h + 0], acc[0][mt][nt][2 * h + 1]);
                }
            }
        }
    }
}

// ---------------- combine: out[t] = shared(out) + sum_k w * yb[slot] ----------------
__global__ void combine_kernel(float* __restrict__ out) {
    int t = blockIdx.x;
    __shared__ int   ss[TOPK];
    __shared__ float sw[TOPK];
    if (threadIdx.x < TOPK) {
        ss[threadIdx.x] = d_slot[t * TOPK + threadIdx.x];
        sw[threadIdx.x] = d_wt[t * TOPK + threadIdx.x];
    }
    __syncthreads();
    float4* orow = (float4*)(out + (size_t)t * H_);
    for (int i = threadIdx.x; i < H_ / 4; i += blockDim.x) {
        float4 o = orow[i];
        #pragma unroll
        for (int k = 0; k < TOPK; k++) {
            int slot = ss[k];
            if (slot < 0) continue;
            float w = sw[k];
            float4 y = ((const float4*)(d_yb + (size_t)slot * H_))[i];
            o.x += w * y.x; o.y += w * y.y; o.z += w * y.z; o.w += w * y.w;
        }
        orow[i] = o;
    }
}

// ---------------- launch ----------------
extern "C" void kernel_launch(void* const* d_in, const int* in_sizes, int n_in,
                              void* d_out, int out_size) {
    const float* x      = (const float*)d_in[0];
    const float* gate_w = (const float*)d_in[1];
    const float* bias   = (const float*)d_in[2];
    const float* w_gate = (const float*)d_in[3];
    const float* w_up   = (const float*)d_in[4];
    const float* w_down = (const float*)d_in[5];
    const float* sg     = (const float*)d_in[6];
    const float* su     = (const float*)d_in[7];
    const float* sd     = (const float*)d_in[8];
    float* out = (float*)d_out;

    cudaFuncSetAttribute(gemm_tc<true>,  cudaFuncAttributeMaxDynamicSharedMemorySize, SMEM_GEMM);
    cudaFuncSetAttribute(gemm_tc<false>, cudaFuncAttributeMaxDynamicSharedMemorySize, SMEM_GEMM);

    init_kernel<<<1, 32>>>();
    round_x_kernel<<<(T_ * H_ / 4) / 256, 256>>>(x);
    router_kernel<<<T_, 128>>>(x, gate_w, bias);

    // fused gate+up (SwiGLU), then down — routed e=0..31 + shared e=32
    gemm_tc<true><<<dim3(I_ / 64, T_ / 128, E_ + 1), 256, SMEM_GEMM>>>(w_gate, w_up, sg, su, nullptr);
    gemm_tc<false><<<dim3(H_ / 128, T_ / 128, E_ + 1), 256, SMEM_GEMM>>>(w_down, nullptr, sd, nullptr, out);

    combine_kernel<<<T_, 256>>>(out);
}